// round 14
// baseline (speedup 1.0000x reference)
#include <cuda_runtime.h>
#include <cuda_bf16.h>
#include <math.h>
#include <stdint.h>

// ---------------- problem constants ----------------
#define BB    256
#define CDDN  5
#define HISN  50
#define TT    20
#define DD    300
#define HH    16
#define VDIM  16
#define RPR   256
#define QDQ   200
#define NITEMS (BB*(CDDN+HISN))   // 14080
#define SCALE 0.05773502691896258f

// GEMM / chunking constants
#define NCHUNK 4
#define ITEMS_PC (NITEMS/NCHUNK)        // 3520
#define ROWS_PC  (ITEMS_PC*TT)          // 70400
#define KP   320
#define NP5  (HH*KP)                    // 5120

// ---------------- device scratch ----------------
__device__ float g_cdd[BB*CDDN*RPR];
__device__ float g_his[BB*HISN*RPR];
__device__ float g_nval[BB*HISN*RPR];
__device__ float g_user[BB*RPR];
__device__ __nv_bfloat16 g_xhi[(size_t)NITEMS*TT*KP];
__device__ __nv_bfloat16 g_xlo[(size_t)NITEMS*TT*KP];
__device__ __nv_bfloat16 g_bhi[KP*NP5];
__device__ __nv_bfloat16 g_blo[KP*NP5];
__device__ float g_q[(size_t)ROWS_PC*NP5];

// ---------------- packed f32x2 helpers ----------------
__device__ __forceinline__ uint64_t pk2(float a, float b){
    uint64_t r; asm("mov.b64 %0,{%1,%2};" : "=l"(r) : "f"(a), "f"(b)); return r;
}
__device__ __forceinline__ void fma2(uint64_t& d, uint64_t a, uint64_t b){
    asm("fma.rn.f32x2 %0,%1,%2,%0;" : "+l"(d) : "l"(a), "l"(b));
}
__device__ __forceinline__ float2 up2(uint64_t v){
    float2 f; asm("mov.b64 {%0,%1},%2;" : "=f"(f.x), "=f"(f.y) : "l"(v)); return f;
}
#define GBAR(id) asm volatile("bar.sync %0, 160;" :: "r"(id) : "memory")

__device__ __forceinline__ uint32_t s2u(const void* p){
    return (uint32_t)__cvta_generic_to_shared(p);
}
__device__ __forceinline__ void ldmx4(uint32_t* r, uint32_t addr){
    asm volatile("ldmatrix.sync.aligned.m8n8.x4.shared.b16 {%0,%1,%2,%3},[%4];"
        : "=r"(r[0]),"=r"(r[1]),"=r"(r[2]),"=r"(r[3]) : "r"(addr));
}
__device__ __forceinline__ void ldmx2t(uint32_t* r, uint32_t addr){
    asm volatile("ldmatrix.sync.aligned.m8n8.x2.trans.shared.b16 {%0,%1},[%2];"
        : "=r"(r[0]),"=r"(r[1]) : "r"(addr));
}
__device__ __forceinline__ void mma16816(float* c, const uint32_t* a, const uint32_t* b){
    asm volatile("mma.sync.aligned.m16n8k16.row.col.f32.bf16.bf16.f32 "
        "{%0,%1,%2,%3},{%4,%5,%6,%7},{%8,%9},{%0,%1,%2,%3};"
        : "+f"(c[0]),"+f"(c[1]),"+f"(c[2]),"+f"(c[3])
        : "r"(a[0]),"r"(a[1]),"r"(a[2]),"r"(a[3]),"r"(b[0]),"r"(b[1]));
}
__device__ __forceinline__ void cpa16(uint32_t d, const void* s){
    asm volatile("cp.async.ca.shared.global [%0],[%1],16;\n" :: "r"(d), "l"(s));
}
#define CPCOMMIT() asm volatile("cp.async.commit_group;\n" ::: "memory")
#define CPWAIT(n)  asm volatile("cp.async.wait_group %0;\n" :: "n"(n) : "memory")

extern __shared__ float sm[];

// ================= weight conversion =================
__global__ void conv_w_kernel(const float* __restrict__ Wq)
{
    int idx = blockIdx.x*256 + threadIdx.x;
    if (idx >= KP*NP5) return;
    int k = idx / NP5, n = idx % NP5;
    int h = n / KP, e = n % KP;
    float v = 0.f;
    if (k < DD && e < DD) v = Wq[h*DD*DD + k*DD + e];
    __nv_bfloat16 hi = __float2bfloat16(v);
    g_bhi[idx] = hi;
    g_blo[idx] = __float2bfloat16(v - __bfloat162float(hi));
}

// ================= x gather + bf16 split =================
__global__ void conv_x_kernel(const int* __restrict__ cand, const int* __restrict__ clicked,
                              const float* __restrict__ emb)
{
    __shared__ int tok[TT];
    const int item = blockIdx.x, tid = threadIdx.x;
    if (tid < TT) {
        const int* tp = (item < BB*CDDN) ? (cand + item*TT)
                                         : (clicked + (item - BB*CDDN)*TT);
        tok[tid] = tp[tid];
    }
    __syncthreads();
    size_t base = (size_t)item*TT*KP;
    for (int p = tid; p < TT*KP; p += 256) {
        int s = p / KP, k = p % KP;
        float v = (k < DD) ? emb[(size_t)tok[s]*DD + k] : 0.f;
        __nv_bfloat16 hi = __float2bfloat16(v);
        g_xhi[base + p] = hi;
        g_xlo[base + p] = __float2bfloat16(v - __bfloat162float(hi));
    }
}

// ================= Q GEMM: cp.async 2-stage, bf16-split mma.sync =================
#define PA 40
#define PB 136
#define ST_ELEM 18944            // per-stage bf16 elems: 2*128*40 + 2*32*136
#define ST_BYTE (ST_ELEM*2)      // 37888
#define OFF_AL  (128*PA)         // 5120
#define OFF_BH  (2*128*PA)       // 10240
#define OFF_BL  (2*128*PA + 32*PB)  // 14592

__global__ __launch_bounds__(512, 1)
void qgemm_kernel(int row_off)
{
    __nv_bfloat16* smb = (__nv_bfloat16*)sm;
    const int tid  = threadIdx.x;
    const int nb   = blockIdx.x;
    const int mb   = blockIdx.y;
    const size_t arow = (size_t)row_off + (size_t)mb*128;

    const int la_r = tid >> 2, la_s = (tid & 3)*8;
    const int lb_r = tid >> 4, lb_s = (tid & 15)*8;
    const __nv_bfloat16* pAh = g_xhi + (arow + la_r)*KP + la_s;
    const __nv_bfloat16* pAl = g_xlo + (arow + la_r)*KP + la_s;
    const __nv_bfloat16* pBh = g_bhi + (size_t)lb_r*NP5 + nb*128 + lb_s;
    const __nv_bfloat16* pBl = g_blo + (size_t)lb_r*NP5 + nb*128 + lb_s;

    const uint32_t smbase = s2u(smb);
    const uint32_t dA  = (uint32_t)((la_r*PA + la_s)*2);
    const uint32_t dB  = (uint32_t)(OFF_BH*2 + (lb_r*PB + lb_s)*2);

    // prologue: stage 0 loads
    cpa16(smbase + dA,              pAh);
    cpa16(smbase + dA + OFF_AL*2,   pAl);
    cpa16(smbase + dB,              pBh);
    cpa16(smbase + dB + 32*PB*2,    pBl);
    CPCOMMIT();

    const int warp = tid >> 5, lane = tid & 31;
    const int wm = warp >> 2, wn = warp & 3;

    float c[2][4][4];
    #pragma unroll
    for (int mt = 0; mt < 2; mt++)
        #pragma unroll
        for (int ns = 0; ns < 4; ns++)
            #pragma unroll
            for (int i = 0; i < 4; i++) c[mt][ns][i] = 0.f;

    const uint32_t offAh = (uint32_t)(((wm*32 + (lane & 15))*PA + (lane >> 4)*8)*2);
    const uint32_t offAl = offAh + OFF_AL*2;
    const uint32_t offBh = (uint32_t)(OFF_BH*2 + ((lane & 15)*PB + wn*32)*2);
    const uint32_t offBl = offBh + 32*PB*2;

    #pragma unroll 1
    for (int ck = 0; ck < 10; ck++) {
        if (ck < 9) {   // issue next stage (other buffer; safe: barrier at end of prev iter)
            uint32_t sb = smbase + ((ck+1)&1)*ST_BYTE;
            cpa16(sb + dA,            pAh + (ck+1)*32);
            cpa16(sb + dA + OFF_AL*2, pAl + (ck+1)*32);
            cpa16(sb + dB,            pBh + (size_t)(ck+1)*32*NP5);
            cpa16(sb + dB + 32*PB*2,  pBl + (size_t)(ck+1)*32*NP5);
            CPCOMMIT();
            CPWAIT(1);          // stage ck complete, ck+1 in flight
        } else {
            CPWAIT(0);
        }
        __syncthreads();

        const uint32_t stg = smbase + (ck&1)*ST_BYTE;
        const uint32_t aAh = stg + offAh, aAl = stg + offAl;
        const uint32_t aBh = stg + offBh, aBl = stg + offBl;
        #pragma unroll
        for (int k16 = 0; k16 < 2; k16++) {
            uint32_t ah[2][4], al[2][4], bh[4][2], bl[4][2];
            #pragma unroll
            for (int mt = 0; mt < 2; mt++) {
                ldmx4(ah[mt], aAh + mt*16*PA*2 + k16*32);
                ldmx4(al[mt], aAl + mt*16*PA*2 + k16*32);
            }
            #pragma unroll
            for (int ns = 0; ns < 4; ns++) {
                ldmx2t(bh[ns], aBh + ns*16 + k16*16*PB*2);
                ldmx2t(bl[ns], aBl + ns*16 + k16*16*PB*2);
            }
            #pragma unroll
            for (int mt = 0; mt < 2; mt++)
                #pragma unroll
                for (int ns = 0; ns < 4; ns++) {
                    mma16816(c[mt][ns], ah[mt], bh[ns]);
                    mma16816(c[mt][ns], ah[mt], bl[ns]);
                    mma16816(c[mt][ns], al[mt], bh[ns]);
                }
        }
        __syncthreads();   // stage ck fully consumed; its buffer reusable at ck+2
    }

    const int orow0 = mb*128 + wm*32;
    #pragma unroll
    for (int mt = 0; mt < 2; mt++)
        #pragma unroll
        for (int ns = 0; ns < 4; ns++) {
            int r   = orow0 + mt*16 + (lane >> 2);
            int col = nb*128 + wn*32 + ns*8 + (lane & 3)*2;
            *(float2*)(g_q + (size_t)r*NP5 + col)     = make_float2(c[mt][ns][0], c[mt][ns][1]);
            *(float2*)(g_q + (size_t)(r+8)*NP5 + col) = make_float2(c[mt][ns][2], c[mt][ns][3]);
        }
}

// ================= word-level encoder =================
// smem: xT[300][24] | qT[4][300][21] | V[20][256] | valT[256][24] | attn[4][20][21] | wl[20]
#define W_XP 24
#define W_QP 21
#define W_QT_OFF  (300*W_XP)                  // 7200
#define W_V_OFF   (W_QT_OFF + 4*300*W_QP)     // 32400
#define W_VAL_OFF (W_V_OFF  + TT*RPR)         // 37520 (x4B = 16-mult)
#define W_ATT_OFF (W_VAL_OFF + 256*24)        // 43664
#define W_WL_OFF  (W_ATT_OFF + 4*TT*21)       // 45344
#define W_SMEM_FLOATS (W_WL_OFF + TT)         // 45364 (~177.2 KB)

__global__ __launch_bounds__(640, 1)
void word_kernel(int item_off,
                 const int* __restrict__ cand, const int* __restrict__ clicked,
                 const float* __restrict__ emb,
                 const float* __restrict__ Wv,
                 const float* __restrict__ Wk, const float* __restrict__ bk,
                 const float* __restrict__ qv)
{
    float* xT   = sm;
    float* qT   = sm + W_QT_OFF;
    float* V    = sm + W_V_OFF;
    float* valT = sm + W_VAL_OFF;
    float* attn = sm + W_ATT_OFF;
    float* wl   = sm + W_WL_OFF;
    __shared__ int tok[TT];

    const int tid   = threadIdx.x;
    const int lit   = blockIdx.x;
    const int item  = item_off + lit;

    const int* tp = (item < BB*CDDN) ? (cand + item*TT)
                                     : (clicked + (item - BB*CDDN)*TT);
    if (tid < TT) tok[tid] = tp[tid];
    __syncthreads();

    for (int p = tid; p < TT*DD; p += 640) {
        int s = p / DD, f = p - s*DD;
        xT[f*W_XP + s] = emb[tok[s]*DD + f];
    }
    __syncthreads();

    // ---- V = x @ Wv_all ----
    for (int p = tid; p < TT*64; p += 640) {
        int s = p >> 6, cq = p & 63, cc = cq*4;
        int h = cc >> 4, v = cc & 15;
        const float* w = Wv + h*(DD*VDIM) + v;
        uint64_t a0 = 0, a1 = 0;
        #pragma unroll 4
        for (int f = 0; f < DD; f++) {
            float xv = xT[f*W_XP + s];
            uint64_t px = pk2(xv, xv);
            ulonglong2 wv = *(const ulonglong2*)(w + f*VDIM);
            fma2(a0, px, wv.x); fma2(a1, px, wv.y);
        }
        float2 r0 = up2(a0), r1 = up2(a1);
        *(float4*)(V + s*RPR + cc) = make_float4(r0.x, r0.y, r1.x, r1.y);
    }
    __syncthreads();

    const int grp  = tid / 160;
    const int t    = tid % 160;
    const int gbar = grp + 1;

    for (int g = 0; g < 4; g++) {
        const int h = g*4 + grp;

        // ---- load Q_h tile from g_q (transposed into qT plane) ----
        {
            const float* qsrc = g_q + (size_t)(lit*TT)*NP5 + h*KP;
            float* qp = qT + grp*(300*W_QP);
            for (int j = t; j < 1500; j += 160) {
                int s = j / 75, c4 = j % 75, e = c4*4;
                float4 q4 = *(const float4*)(qsrc + (size_t)s*NP5 + e);
                qp[(e+0)*W_QP + s] = q4.x;
                qp[(e+1)*W_QP + s] = q4.y;
                qp[(e+2)*W_QP + s] = q4.z;
                qp[(e+3)*W_QP + s] = q4.w;
            }
        }
        GBAR(gbar);

        // ---- logits ----
        if (t < 100) {
            int s = t % 20, uq = t / 20;
            const float* qh = qT + grp*(300*W_QP);
            uint64_t a0 = 0, a1 = 0;
            #pragma unroll 4
            for (int e = 0; e < DD; e++) {
                float q = qh[e*W_QP + s];
                uint64_t pq = pk2(q, q);
                ulonglong2 xv = *(const ulonglong2*)(xT + e*W_XP + uq*4);
                fma2(a0, pq, xv.x); fma2(a1, pq, xv.y);
            }
            float2 r0 = up2(a0), r1 = up2(a1);
            float* ar = attn + (grp*TT + s)*21 + uq*4;
            ar[0]=r0.x*SCALE; ar[1]=r0.y*SCALE; ar[2]=r1.x*SCALE; ar[3]=r1.y*SCALE;
        }
        GBAR(gbar);

        // ---- softmax ----
        if (t < 20) {
            float* row = attn + (grp*TT + t)*21;
            float m = row[0];
            #pragma unroll
            for (int u = 1; u < TT; u++) m = fmaxf(m, row[u]);
            float sum = 0.f;
            #pragma unroll
            for (int u = 0; u < TT; u++) { float e = __expf(row[u]-m); row[u]=e; sum+=e; }
            float inv = 1.f/sum;
            #pragma unroll
            for (int u = 0; u < TT; u++) row[u] *= inv;
        }
        GBAR(gbar);

        // ---- val = attn @ V -> valT (transposed store) ----
        #pragma unroll
        for (int j = 0; j < 2; j++) {
            int p = t + j*160;
            int s = p >> 4, v = p & 15;
            const float* ar = attn + (grp*TT + s)*21;
            const float* vc = V + h*VDIM + v;
            float a = 0.f;
            #pragma unroll
            for (int u = 0; u < TT; u++) a += ar[u]*vc[u*RPR];
            valT[(h*VDIM + v)*24 + s] = a;
        }
        GBAR(gbar);
    }
    __syncthreads();

    // ---- additive pooling: thread-per-k, Wk read ONCE per item ----
    if (tid < TT) wl[tid] = 0.f;
    __syncthreads();
    if (tid < QDQ) {
        const int k = tid;
        const float bkk = bk[k];
        uint64_t acc[10];
        #pragma unroll
        for (int j = 0; j < 10; j++) acc[j] = pk2(bkk, bkk);
        const float* wkp = Wk + k;
        #pragma unroll 4
        for (int r = 0; r < RPR; r++) {
            float w = wkp[r*QDQ];
            uint64_t pw = pk2(w, w);
            const ulonglong2* vr = (const ulonglong2*)(valT + r*24);
            ulonglong2 v0 = vr[0], v1 = vr[1], v2 = vr[2], v3 = vr[3], v4 = vr[4];
            fma2(acc[0], v0.x, pw); fma2(acc[1], v0.y, pw);
            fma2(acc[2], v1.x, pw); fma2(acc[3], v1.y, pw);
            fma2(acc[4], v2.x, pw); fma2(acc[5], v2.y, pw);
            fma2(acc[6], v3.x, pw); fma2(acc[7], v3.y, pw);
            fma2(acc[8], v4.x, pw); fma2(acc[9], v4.y, pw);
        }
        const float qvk = qv[k];
        #pragma unroll
        for (int j = 0; j < 10; j++) {
            float2 p = up2(acc[j]);
            atomicAdd(&wl[2*j],   tanhf(p.x)*qvk);
            atomicAdd(&wl[2*j+1], tanhf(p.y)*qvk);
        }
    }
    __syncthreads();
    if (tid == 0) {
        float m = -1e30f;
        for (int s = 0; s < TT; s++) { wl[s] *= SCALE; m = fmaxf(m, wl[s]); }
        float sum = 0.f;
        for (int s = 0; s < TT; s++) { float e = __expf(wl[s]-m); wl[s]=e; sum+=e; }
        float inv = 1.f/sum;
        for (int s = 0; s < TT; s++) wl[s] *= inv;
    }
    __syncthreads();
    if (tid < RPR) {
        const float* vb = valT + tid*24;
        float a = 0.f;
        #pragma unroll
        for (int s = 0; s < TT; s++) a += wl[s] * vb[s];
        float* outp = (item < BB*CDDN) ? (g_cdd + item*RPR)
                                       : (g_his + (item - BB*CDDN)*RPR);
        outp[tid] = a;
    }
}

// ================= news level (unchanged) =================
#define NA_XP 52
#define NA_QP 51
#define NA_QT_OFF (256*NA_XP)
#define NA_AT_OFF (NA_QT_OFF + 256*NA_QP)
#define NA_V_OFF  (NA_AT_OFF + 50*51 + 2)
#define NA_SMEM_FLOATS (NA_V_OFF + 50*16)

__global__ __launch_bounds__(256, 1)
void news_attn_kernel(const float* __restrict__ Wq, const float* __restrict__ Wv)
{
    float* xT   = sm;
    float* qT   = sm + NA_QT_OFF;
    float* attn = sm + NA_AT_OFF;
    float* Vh   = sm + NA_V_OFF;

    const int tid = threadIdx.x;
    const int h   = blockIdx.x;
    const int b   = blockIdx.y;
    const float* x = g_his + b*HISN*RPR;

    for (int p = tid; p < HISN*RPR; p += 256) {
        int f = p & 255, s = p >> 8;
        xT[f*NA_XP + s] = x[p];
    }
    for (int p = tid; p < 512; p += 256)
        xT[(p>>1)*NA_XP + 50 + (p&1)] = 0.f;
    __syncthreads();

    if (tid < 200) {
        int s = tid >> 2, v = (tid & 3)*4;
        const float* w = Wv + h*(RPR*VDIM) + v;
        uint64_t a0 = 0, a1 = 0;
        #pragma unroll 4
        for (int f = 0; f < RPR; f++) {
            float xv = xT[f*NA_XP + s];
            uint64_t px = pk2(xv, xv);
            ulonglong2 wv = *(const ulonglong2*)(w + f*VDIM);
            fma2(a0, px, wv.x); fma2(a1, px, wv.y);
        }
        float2 r0 = up2(a0), r1 = up2(a1);
        *(float4*)(Vh + s*16 + v) = make_float4(r0.x, r0.y, r1.x, r1.y);
    }

    {
        uint64_t acc[25];
        #pragma unroll
        for (int k = 0; k < 25; k++) acc[k] = 0ull;
        const float* wq = Wq + (size_t)h*(RPR*RPR) + tid;
        float w0 = wq[0];
        float w1 = wq[RPR];
        #pragma unroll 1
        for (int f = 0; f < RPR; f += 2) {
            int fn = (f + 2 < RPR) ? (f + 2) : 0;
            float n0 = wq[fn*RPR];
            float n1 = wq[(fn+1)*RPR];
            {
                uint64_t pw = pk2(w0, w0);
                const ulonglong2* xr = (const ulonglong2*)(xT + f*NA_XP);
                #pragma unroll
                for (int k = 0; k < 12; k++) {
                    ulonglong2 xv = xr[k];
                    fma2(acc[2*k],   xv.x, pw);
                    fma2(acc[2*k+1], xv.y, pw);
                }
                uint64_t xt = *(const uint64_t*)(xT + f*NA_XP + 48);
                fma2(acc[24], xt, pw);
            }
            {
                uint64_t pw = pk2(w1, w1);
                const ulonglong2* xr = (const ulonglong2*)(xT + (f+1)*NA_XP);
                #pragma unroll
                for (int k = 0; k < 12; k++) {
                    ulonglong2 xv = xr[k];
                    fma2(acc[2*k],   xv.x, pw);
                    fma2(acc[2*k+1], xv.y, pw);
                }
                uint64_t xt = *(const uint64_t*)(xT + (f+1)*NA_XP + 48);
                fma2(acc[24], xt, pw);
            }
            w0 = n0; w1 = n1;
        }
        float* q0 = qT + tid*NA_QP;
        #pragma unroll
        for (int k = 0; k < 25; k++) {
            float2 a = up2(acc[k]); q0[2*k] = a.x; q0[2*k+1] = a.y;
        }
    }
    __syncthreads();

    for (int p = tid; p < 650; p += 256) {
        int s = p % 50, uq = p / 50, u = uq*4;
        uint64_t a0 = 0, a1 = 0;
        #pragma unroll 4
        for (int e = 0; e < RPR; e++) {
            float q = qT[e*NA_QP + s];
            uint64_t pq = pk2(q, q);
            ulonglong2 xv = *(const ulonglong2*)(xT + e*NA_XP + u);
            fma2(a0, pq, xv.x); fma2(a1, pq, xv.y);
        }
        float2 r0 = up2(a0), r1 = up2(a1);
        float* ar = attn + s*51;
        ar[u] = r0.x*SCALE;
        if (u+1 < 50) ar[u+1] = r0.y*SCALE;
        if (u+2 < 50) { ar[u+2] = r1.x*SCALE; ar[u+3] = r1.y*SCALE; }
    }
    __syncthreads();

    if (tid < 50) {
        float* row = attn + tid*51;
        float m = row[0];
        for (int u = 1; u < 50; u++) m = fmaxf(m, row[u]);
        float sum = 0.f;
        for (int u = 0; u < 50; u++) { float e = __expf(row[u]-m); row[u]=e; sum+=e; }
        float inv = 1.f/sum;
        for (int u = 0; u < 50; u++) row[u] *= inv;
    }
    __syncthreads();

    for (int p = tid; p < 800; p += 256) {
        int s = p >> 4, v = p & 15;
        const float* ar = attn + s*51;
        float a = 0.f;
        #pragma unroll 10
        for (int u = 0; u < 50; u++) a += ar[u]*Vh[u*16 + v];
        g_nval[(b*HISN + s)*RPR + h*VDIM + v] = a;
    }
}

#define NP_SMEM_FLOATS (HISN*RPR + HISN)

__global__ __launch_bounds__(256, 2)
void news_pool_kernel(const float* __restrict__ Wk, const float* __restrict__ bk,
                      const float* __restrict__ qv)
{
    float* val = sm;
    float* wl  = sm + HISN*RPR;
    const int tid = threadIdx.x;
    const int b   = blockIdx.x;

    for (int p = tid; p < HISN*RPR; p += 256) val[p] = g_nval[b*HISN*RPR + p];
    if (tid < HISN) wl[tid] = 0.f;
    __syncthreads();

    for (int p = tid; p < HISN*50; p += 256) {
        int s = p/50, kq = p%50, k = kq*4;
        float4 b4 = *(const float4*)(bk + k);
        uint64_t a0 = pk2(b4.x, b4.y), a1 = pk2(b4.z, b4.w);
        const float* vr  = val + s*RPR;
        const float* wkp = Wk + k;
        #pragma unroll 8
        for (int r = 0; r < RPR; r++) {
            uint64_t pv = pk2(vr[r], vr[r]);
            ulonglong2 wv = *(const ulonglong2*)(wkp + r*QDQ);
            fma2(a0, pv, wv.x); fma2(a1, pv, wv.y);
        }
        float2 r0 = up2(a0), r1 = up2(a1);
        float4 q4 = *(const float4*)(qv + k);
        float ts = tanhf(r0.x)*q4.x + tanhf(r0.y)*q4.y + tanhf(r1.x)*q4.z + tanhf(r1.y)*q4.w;
        atomicAdd(&wl[s], ts);
    }
    __syncthreads();
    if (tid == 0) {
        float m = -1e30f;
        for (int s = 0; s < HISN; s++) { wl[s] *= SCALE; m = fmaxf(m, wl[s]); }
        float sum = 0.f;
        for (int s = 0; s < HISN; s++) { float e = __expf(wl[s]-m); wl[s]=e; sum+=e; }
        float inv = 1.f/sum;
        for (int s = 0; s < HISN; s++) wl[s] *= inv;
    }
    __syncthreads();
    if (tid < RPR) {
        float a = 0.f;
        #pragma unroll 10
        for (int s = 0; s < HISN; s++) a += wl[s] * val[s*RPR + tid];
        g_user[b*RPR + tid] = a;
    }
}

__global__ void score_kernel(float* __restrict__ out)
{
    __shared__ float sc[CDDN];
    const int b = blockIdx.x;
    const int w = threadIdx.x >> 5, lane = threadIdx.x & 31;
    if (w < CDDN) {
        const float* c = g_cdd + (b*CDDN + w)*RPR;
        const float* u = g_user + b*RPR;
        float a = 0.f;
        #pragma unroll
        for (int k = lane; k < RPR; k += 32) a += c[k]*u[k];
        #pragma unroll
        for (int off = 16; off; off >>= 1) a += __shfl_down_sync(0xffffffffu, a, off);
        if (lane == 0) sc[w] = a;
    }
    __syncthreads();
    if (threadIdx.x == 0) {
        float m = sc[0];
        for (int c = 1; c < CDDN; c++) m = fmaxf(m, sc[c]);
        float sum = 0.f;
        for (int c = 0; c < CDDN; c++) sum += __expf(sc[c]-m);
        float lse = logf(sum) + m;
        for (int c = 0; c < CDDN; c++) out[b*CDDN + c] = sc[c] - lse;
    }
}

// ================= launch =================
extern "C" void kernel_launch(void* const* d_in, const int* in_sizes, int n_in,
                              void* d_out, int out_size)
{
    (void)in_sizes; (void)n_in; (void)out_size;
    const int*   cand    = (const int*)d_in[0];
    const int*   clicked = (const int*)d_in[1];
    const float* emb     = (const float*)d_in[2];
    const float* Wq_w    = (const float*)d_in[3];
    const float* Wv_w    = (const float*)d_in[4];
    const float* Wk_w    = (const float*)d_in[5];
    const float* bk_w    = (const float*)d_in[6];
    const float* q_w     = (const float*)d_in[7];
    const float* Wq_n    = (const float*)d_in[8];
    const float* Wv_n    = (const float*)d_in[9];
    const float* Wk_n    = (const float*)d_in[10];
    const float* bk_n    = (const float*)d_in[11];
    const float* q_n     = (const float*)d_in[12];
    float* out = (float*)d_out;

    const size_t smw  = W_SMEM_FLOATS  * sizeof(float);
    const size_t smna = NA_SMEM_FLOATS * sizeof(float);
    const size_t smnp = NP_SMEM_FLOATS * sizeof(float);
    const size_t smg  = 2*ST_BYTE;   // 75776 B
    cudaFuncSetAttribute(word_kernel,      cudaFuncAttributeMaxDynamicSharedMemorySize, (int)smw);
    cudaFuncSetAttribute(news_attn_kernel, cudaFuncAttributeMaxDynamicSharedMemorySize, (int)smna);
    cudaFuncSetAttribute(news_pool_kernel, cudaFuncAttributeMaxDynamicSharedMemorySize, (int)smnp);
    cudaFuncSetAttribute(qgemm_kernel,     cudaFuncAttributeMaxDynamicSharedMemorySize, (int)smg);

    conv_w_kernel<<<(KP*NP5 + 255)/256, 256>>>(Wq_w);
    conv_x_kernel<<<NITEMS, 256>>>(cand, clicked, emb);

    for (int ch = 0; ch < NCHUNK; ch++) {
        qgemm_kernel<<<dim3(NP5/128, ROWS_PC/128), 512, smg>>>(ch*ROWS_PC);
        word_kernel<<<ITEMS_PC, 640, smw>>>(ch*ITEMS_PC, cand, clicked, emb,
                                            Wv_w, Wk_w, bk_w, q_w);
    }

    news_attn_kernel<<<dim3(HH, BB), 256, smna>>>(Wq_n, Wv_n);
    news_pool_kernel<<<BB, 256, smnp>>>(Wk_n, bk_n, q_n);
    score_kernel<<<BB, 192>>>(out);
}

// round 15
// speedup vs baseline: 1.5476x; 1.5476x over previous
#include <cuda_runtime.h>
#include <cuda_bf16.h>
#include <math.h>
#include <stdint.h>

// ---------------- problem constants ----------------
#define BB    256
#define CDDN  5
#define HISN  50
#define TT    20
#define DD    300
#define HH    16
#define VDIM  16
#define RPR   256
#define QDQ   200
#define NITEMS (BB*(CDDN+HISN))   // 14080
#define SCALE 0.05773502691896258f

// GEMM / chunking constants
#define NCHUNK 4
#define ITEMS_PC (NITEMS/NCHUNK)        // 3520
#define ROWS_PC  (ITEMS_PC*TT)          // 70400
#define KP   320
#define NQ   (HH*KP)                    // 5120 (Q columns)
#define NPX  (NQ + RPR)                 // 5376 (Q + V columns)

// ---------------- device scratch ----------------
__device__ float g_cdd[BB*CDDN*RPR];
__device__ float g_his[BB*HISN*RPR];
__device__ float g_nval[BB*HISN*RPR];
__device__ float g_user[BB*RPR];
__device__ __nv_bfloat16 g_xhi[(size_t)NITEMS*TT*KP];
__device__ __nv_bfloat16 g_xlo[(size_t)NITEMS*TT*KP];
__device__ __nv_bfloat16 g_bhi[KP*NPX];
__device__ __nv_bfloat16 g_blo[KP*NPX];
__device__ float g_q[(size_t)ROWS_PC*NPX];   // 1.51 GB (per chunk)

// ---------------- packed f32x2 helpers ----------------
__device__ __forceinline__ uint64_t pk2(float a, float b){
    uint64_t r; asm("mov.b64 %0,{%1,%2};" : "=l"(r) : "f"(a), "f"(b)); return r;
}
__device__ __forceinline__ void fma2(uint64_t& d, uint64_t a, uint64_t b){
    asm("fma.rn.f32x2 %0,%1,%2,%0;" : "+l"(d) : "l"(a), "l"(b));
}
__device__ __forceinline__ float2 up2(uint64_t v){
    float2 f; asm("mov.b64 {%0,%1},%2;" : "=f"(f.x), "=f"(f.y) : "l"(v)); return f;
}
#define GBAR(id) asm volatile("bar.sync %0, 160;" :: "r"(id) : "memory")

__device__ __forceinline__ uint32_t s2u(const void* p){
    return (uint32_t)__cvta_generic_to_shared(p);
}
__device__ __forceinline__ void ldmx4(uint32_t* r, uint32_t addr){
    asm volatile("ldmatrix.sync.aligned.m8n8.x4.shared.b16 {%0,%1,%2,%3},[%4];"
        : "=r"(r[0]),"=r"(r[1]),"=r"(r[2]),"=r"(r[3]) : "r"(addr));
}
__device__ __forceinline__ void ldmx2t(uint32_t* r, uint32_t addr){
    asm volatile("ldmatrix.sync.aligned.m8n8.x2.trans.shared.b16 {%0,%1},[%2];"
        : "=r"(r[0]),"=r"(r[1]) : "r"(addr));
}
__device__ __forceinline__ void mma16816(float* c, const uint32_t* a, const uint32_t* b){
    asm volatile("mma.sync.aligned.m16n8k16.row.col.f32.bf16.bf16.f32 "
        "{%0,%1,%2,%3},{%4,%5,%6,%7},{%8,%9},{%0,%1,%2,%3};"
        : "+f"(c[0]),"+f"(c[1]),"+f"(c[2]),"+f"(c[3])
        : "r"(a[0]),"r"(a[1]),"r"(a[2]),"r"(a[3]),"r"(b[0]),"r"(b[1]));
}

extern __shared__ float sm[];

// ================= weight conversion: [Wq | Wv] -> bf16 hi/lo B [KP][NPX] =================
__global__ void conv_w_kernel(const float* __restrict__ Wq, const float* __restrict__ Wv)
{
    int idx = blockIdx.x*256 + threadIdx.x;
    if (idx >= KP*NPX) return;
    int k = idx / NPX, n = idx % NPX;
    float v = 0.f;
    if (n < NQ) {
        int h = n / KP, e = n % KP;
        if (k < DD && e < DD) v = Wq[h*DD*DD + k*DD + e];
    } else {
        int c = n - NQ;
        int h = c >> 4, vv = c & 15;
        if (k < DD) v = Wv[(h*DD + k)*VDIM + vv];
    }
    __nv_bfloat16 hi = __float2bfloat16(v);
    g_bhi[idx] = hi;
    g_blo[idx] = __float2bfloat16(v - __bfloat162float(hi));
}

// ================= x gather + bf16 split =================
__global__ void conv_x_kernel(const int* __restrict__ cand, const int* __restrict__ clicked,
                              const float* __restrict__ emb)
{
    __shared__ int tok[TT];
    const int item = blockIdx.x, tid = threadIdx.x;
    if (tid < TT) {
        const int* tp = (item < BB*CDDN) ? (cand + item*TT)
                                         : (clicked + (item - BB*CDDN)*TT);
        tok[tid] = tp[tid];
    }
    __syncthreads();
    size_t base = (size_t)item*TT*KP;
    for (int p = tid; p < TT*KP; p += 256) {
        int s = p / KP, k = p % KP;
        float v = (k < DD) ? emb[(size_t)tok[s]*DD + k] : 0.f;
        __nv_bfloat16 hi = __float2bfloat16(v);
        g_xhi[base + p] = hi;
        g_xlo[base + p] = __float2bfloat16(v - __bfloat162float(hi));
    }
}

// ================= Q+V GEMM: [128 x 128] tiles, bf16-split mma.sync (R12 structure) =================
#define PA 40
#define PB 136

__global__ __launch_bounds__(512, 1)
void qgemm_kernel(int row_off)
{
    __shared__ __nv_bfloat16 Ah[128*PA], Al[128*PA];
    __shared__ __nv_bfloat16 Bh[32*PB],  Bl[32*PB];

    const int tid  = threadIdx.x;
    const int nb   = blockIdx.x;   // 0..41
    const int mb   = blockIdx.y;   // 0..549
    const size_t arow = (size_t)row_off + (size_t)mb*128;

    const int la_r = tid >> 2, la_s = (tid & 3)*8;
    const int lb_r = tid >> 4, lb_s = (tid & 15)*8;
    const __nv_bfloat16* pAh = g_xhi + (arow + la_r)*KP + la_s;
    const __nv_bfloat16* pAl = g_xlo + (arow + la_r)*KP + la_s;
    const __nv_bfloat16* pBh = g_bhi + (size_t)lb_r*NPX + nb*128 + lb_s;
    const __nv_bfloat16* pBl = g_blo + (size_t)lb_r*NPX + nb*128 + lb_s;

    uint4 rah = *(const uint4*)(pAh);
    uint4 ral = *(const uint4*)(pAl);
    uint4 rbh = *(const uint4*)(pBh);
    uint4 rbl = *(const uint4*)(pBl);
    *(uint4*)(Ah + la_r*PA + la_s) = rah;
    *(uint4*)(Al + la_r*PA + la_s) = ral;
    *(uint4*)(Bh + lb_r*PB + lb_s) = rbh;
    *(uint4*)(Bl + lb_r*PB + lb_s) = rbl;
    __syncthreads();

    const int warp = tid >> 5, lane = tid & 31;
    const int wm = warp >> 2, wn = warp & 3;

    float c[2][4][4];
    #pragma unroll
    for (int mt = 0; mt < 2; mt++)
        #pragma unroll
        for (int ns = 0; ns < 4; ns++)
            #pragma unroll
            for (int i = 0; i < 4; i++) c[mt][ns][i] = 0.f;

    const uint32_t aAh = s2u(Ah) + (uint32_t)(((wm*32 + (lane & 15))*PA + (lane >> 4)*8) * 2);
    const uint32_t aAl = s2u(Al) + (uint32_t)(((wm*32 + (lane & 15))*PA + (lane >> 4)*8) * 2);
    const uint32_t aBh = s2u(Bh) + (uint32_t)(((lane & 15)*PB + wn*32) * 2);
    const uint32_t aBl = s2u(Bl) + (uint32_t)(((lane & 15)*PB + wn*32) * 2);

    #pragma unroll 1
    for (int ck = 0; ck < 10; ck++) {
        if (ck < 9) {
            rah = *(const uint4*)(pAh + (ck+1)*32);
            ral = *(const uint4*)(pAl + (ck+1)*32);
            rbh = *(const uint4*)(pBh + (size_t)(ck+1)*32*NPX);
            rbl = *(const uint4*)(pBl + (size_t)(ck+1)*32*NPX);
        }
        #pragma unroll
        for (int k16 = 0; k16 < 2; k16++) {
            uint32_t ah[2][4], al[2][4], bh[4][2], bl[4][2];
            #pragma unroll
            for (int mt = 0; mt < 2; mt++) {
                ldmx4(ah[mt], aAh + mt*16*PA*2 + k16*32);
                ldmx4(al[mt], aAl + mt*16*PA*2 + k16*32);
            }
            #pragma unroll
            for (int ns = 0; ns < 4; ns++) {
                ldmx2t(bh[ns], aBh + ns*16 + k16*16*PB*2);
                ldmx2t(bl[ns], aBl + ns*16 + k16*16*PB*2);
            }
            #pragma unroll
            for (int mt = 0; mt < 2; mt++)
                #pragma unroll
                for (int ns = 0; ns < 4; ns++) {
                    mma16816(c[mt][ns], ah[mt], bh[ns]);
                    mma16816(c[mt][ns], ah[mt], bl[ns]);
                    mma16816(c[mt][ns], al[mt], bh[ns]);
                }
        }
        __syncthreads();
        if (ck < 9) {
            *(uint4*)(Ah + la_r*PA + la_s) = rah;
            *(uint4*)(Al + la_r*PA + la_s) = ral;
            *(uint4*)(Bh + lb_r*PB + lb_s) = rbh;
            *(uint4*)(Bl + lb_r*PB + lb_s) = rbl;
        }
        __syncthreads();
    }

    const int orow0 = mb*128 + wm*32;
    #pragma unroll
    for (int mt = 0; mt < 2; mt++)
        #pragma unroll
        for (int ns = 0; ns < 4; ns++) {
            int r   = orow0 + mt*16 + (lane >> 2);
            int col = nb*128 + wn*32 + ns*8 + (lane & 3)*2;
            *(float2*)(g_q + (size_t)r*NPX + col)     = make_float2(c[mt][ns][0], c[mt][ns][1]);
            *(float2*)(g_q + (size_t)(r+8)*NPX + col) = make_float2(c[mt][ns][2], c[mt][ns][3]);
        }
}

// ================= word-level encoder (Q and V read from g_q) =================
#define W_XP 24
#define W_QP 21
#define W_QT_OFF  (300*W_XP)
#define W_V_OFF   (W_QT_OFF + 4*300*W_QP)
#define W_VAL_OFF (W_V_OFF  + TT*RPR)
#define W_ATT_OFF (W_VAL_OFF + TT*RPR)
#define W_WL_OFF  (W_ATT_OFF + 4*TT*21)
#define W_SMEM_FLOATS (W_WL_OFF + TT)        // 44340 (177.4 KB)

__global__ __launch_bounds__(640, 1)
void word_kernel(int item_off,
                 const int* __restrict__ cand, const int* __restrict__ clicked,
                 const float* __restrict__ emb,
                 const float* __restrict__ Wk, const float* __restrict__ bk,
                 const float* __restrict__ qv)
{
    float* xT   = sm;
    float* qT   = sm + W_QT_OFF;
    float* V    = sm + W_V_OFF;
    float* val  = sm + W_VAL_OFF;
    float* attn = sm + W_ATT_OFF;
    float* wl   = sm + W_WL_OFF;
    __shared__ int tok[TT];

    const int tid   = threadIdx.x;
    const int lit   = blockIdx.x;
    const int item  = item_off + lit;

    const int* tp = (item < BB*CDDN) ? (cand + item*TT)
                                     : (clicked + (item - BB*CDDN)*TT);
    if (tid < TT) tok[tid] = tp[tid];
    __syncthreads();

    for (int p = tid; p < TT*DD; p += 640) {
        int s = p / DD, f = p - s*DD;
        xT[f*W_XP + s] = emb[tok[s]*DD + f];
    }

    // ---- V: straight copy from GEMM output (cols NQ..NQ+255) ----
    for (int p = tid; p < TT*64; p += 640) {
        int s = p >> 6, c4 = (p & 63)*4;
        float4 q4 = *(const float4*)(g_q + (size_t)(lit*TT + s)*NPX + NQ + c4);
        *(float4*)(V + s*RPR + c4) = q4;
    }
    __syncthreads();

    const int grp  = tid / 160;
    const int t    = tid % 160;
    const int gbar = grp + 1;

    for (int g = 0; g < 4; g++) {
        const int h = g*4 + grp;

        // ---- load Q_h tile from g_q (transposed into qT plane) ----
        {
            const float* qsrc = g_q + (size_t)(lit*TT)*NPX + h*KP;
            float* qp = qT + grp*(300*W_QP);
            for (int j = t; j < 1500; j += 160) {
                int s = j / 75, c4 = j % 75, e = c4*4;
                float4 q4 = *(const float4*)(qsrc + (size_t)s*NPX + e);
                qp[(e+0)*W_QP + s] = q4.x;
                qp[(e+1)*W_QP + s] = q4.y;
                qp[(e+2)*W_QP + s] = q4.z;
                qp[(e+3)*W_QP + s] = q4.w;
            }
        }
        GBAR(gbar);

        // ---- logits ----
        if (t < 100) {
            int s = t % 20, uq = t / 20;
            const float* qh = qT + grp*(300*W_QP);
            uint64_t a0 = 0, a1 = 0;
            #pragma unroll 4
            for (int e = 0; e < DD; e++) {
                float q = qh[e*W_QP + s];
                uint64_t pq = pk2(q, q);
                ulonglong2 xv = *(const ulonglong2*)(xT + e*W_XP + uq*4);
                fma2(a0, pq, xv.x); fma2(a1, pq, xv.y);
            }
            float2 r0 = up2(a0), r1 = up2(a1);
            float* ar = attn + (grp*TT + s)*21 + uq*4;
            ar[0]=r0.x*SCALE; ar[1]=r0.y*SCALE; ar[2]=r1.x*SCALE; ar[3]=r1.y*SCALE;
        }
        GBAR(gbar);

        // ---- softmax ----
        if (t < 20) {
            float* row = attn + (grp*TT + t)*21;
            float m = row[0];
            #pragma unroll
            for (int u = 1; u < TT; u++) m = fmaxf(m, row[u]);
            float sum = 0.f;
            #pragma unroll
            for (int u = 0; u < TT; u++) { float e = __expf(row[u]-m); row[u]=e; sum+=e; }
            float inv = 1.f/sum;
            #pragma unroll
            for (int u = 0; u < TT; u++) row[u] *= inv;
        }
        GBAR(gbar);

        // ---- val = attn @ V ----
        #pragma unroll
        for (int j = 0; j < 2; j++) {
            int p = t + j*160;
            int s = p >> 4, v = p & 15;
            const float* ar = attn + (grp*TT + s)*21;
            const float* vc = V + h*VDIM + v;
            float a = 0.f;
            #pragma unroll
            for (int u = 0; u < TT; u++) a += ar[u]*vc[u*RPR];
            val[s*RPR + h*VDIM + v] = a;
        }
        GBAR(gbar);
    }
    __syncthreads();

    // ---- additive pooling (R12 style) ----
    if (tid < TT) wl[tid] = 0.f;
    __syncthreads();
    for (int p = tid; p < TT*50; p += 640) {
        int s = p/50, kq = p%50, k = kq*4;
        float4 b4 = *(const float4*)(bk + k);
        uint64_t a0 = pk2(b4.x, b4.y), a1 = pk2(b4.z, b4.w);
        const float* vr  = val + s*RPR;
        const float* wkp = Wk + k;
        #pragma unroll 8
        for (int r = 0; r < RPR; r++) {
            uint64_t pv = pk2(vr[r], vr[r]);
            ulonglong2 wv = *(const ulonglong2*)(wkp + r*QDQ);
            fma2(a0, pv, wv.x); fma2(a1, pv, wv.y);
        }
        float2 r0 = up2(a0), r1 = up2(a1);
        float4 q4 = *(const float4*)(qv + k);
        float ts = tanhf(r0.x)*q4.x + tanhf(r0.y)*q4.y + tanhf(r1.x)*q4.z + tanhf(r1.y)*q4.w;
        atomicAdd(&wl[s], ts);
    }
    __syncthreads();
    if (tid == 0) {
        float m = -1e30f;
        for (int s = 0; s < TT; s++) { wl[s] *= SCALE; m = fmaxf(m, wl[s]); }
        float sum = 0.f;
        for (int s = 0; s < TT; s++) { float e = __expf(wl[s]-m); wl[s]=e; sum+=e; }
        float inv = 1.f/sum;
        for (int s = 0; s < TT; s++) wl[s] *= inv;
    }
    __syncthreads();
    if (tid < RPR) {
        float a = 0.f;
        #pragma unroll
        for (int s = 0; s < TT; s++) a += wl[s] * val[s*RPR + tid];
        float* outp = (item < BB*CDDN) ? (g_cdd + item*RPR)
                                       : (g_his + (item - BB*CDDN)*RPR);
        outp[tid] = a;
    }
}

// ================= news level (unchanged) =================
#define NA_XP 52
#define NA_QP 51
#define NA_QT_OFF (256*NA_XP)
#define NA_AT_OFF (NA_QT_OFF + 256*NA_QP)
#define NA_V_OFF  (NA_AT_OFF + 50*51 + 2)
#define NA_SMEM_FLOATS (NA_V_OFF + 50*16)

__global__ __launch_bounds__(256, 1)
void news_attn_kernel(const float* __restrict__ Wq, const float* __restrict__ Wv)
{
    float* xT   = sm;
    float* qT   = sm + NA_QT_OFF;
    float* attn = sm + NA_AT_OFF;
    float* Vh   = sm + NA_V_OFF;

    const int tid = threadIdx.x;
    const int h   = blockIdx.x;
    const int b   = blockIdx.y;
    const float* x = g_his + b*HISN*RPR;

    for (int p = tid; p < HISN*RPR; p += 256) {
        int f = p & 255, s = p >> 8;
        xT[f*NA_XP + s] = x[p];
    }
    for (int p = tid; p < 512; p += 256)
        xT[(p>>1)*NA_XP + 50 + (p&1)] = 0.f;
    __syncthreads();

    if (tid < 200) {
        int s = tid >> 2, v = (tid & 3)*4;
        const float* w = Wv + h*(RPR*VDIM) + v;
        uint64_t a0 = 0, a1 = 0;
        #pragma unroll 4
        for (int f = 0; f < RPR; f++) {
            float xv = xT[f*NA_XP + s];
            uint64_t px = pk2(xv, xv);
            ulonglong2 wv = *(const ulonglong2*)(w + f*VDIM);
            fma2(a0, px, wv.x); fma2(a1, px, wv.y);
        }
        float2 r0 = up2(a0), r1 = up2(a1);
        *(float4*)(Vh + s*16 + v) = make_float4(r0.x, r0.y, r1.x, r1.y);
    }

    {
        uint64_t acc[25];
        #pragma unroll
        for (int k = 0; k < 25; k++) acc[k] = 0ull;
        const float* wq = Wq + (size_t)h*(RPR*RPR) + tid;
        float w0 = wq[0];
        float w1 = wq[RPR];
        #pragma unroll 1
        for (int f = 0; f < RPR; f += 2) {
            int fn = (f + 2 < RPR) ? (f + 2) : 0;
            float n0 = wq[fn*RPR];
            float n1 = wq[(fn+1)*RPR];
            {
                uint64_t pw = pk2(w0, w0);
                const ulonglong2* xr = (const ulonglong2*)(xT + f*NA_XP);
                #pragma unroll
                for (int k = 0; k < 12; k++) {
                    ulonglong2 xv = xr[k];
                    fma2(acc[2*k],   xv.x, pw);
                    fma2(acc[2*k+1], xv.y, pw);
                }
                uint64_t xt = *(const uint64_t*)(xT + f*NA_XP + 48);
                fma2(acc[24], xt, pw);
            }
            {
                uint64_t pw = pk2(w1, w1);
                const ulonglong2* xr = (const ulonglong2*)(xT + (f+1)*NA_XP);
                #pragma unroll
                for (int k = 0; k < 12; k++) {
                    ulonglong2 xv = xr[k];
                    fma2(acc[2*k],   xv.x, pw);
                    fma2(acc[2*k+1], xv.y, pw);
                }
                uint64_t xt = *(const uint64_t*)(xT + (f+1)*NA_XP + 48);
                fma2(acc[24], xt, pw);
            }
            w0 = n0; w1 = n1;
        }
        float* q0 = qT + tid*NA_QP;
        #pragma unroll
        for (int k = 0; k < 25; k++) {
            float2 a = up2(acc[k]); q0[2*k] = a.x; q0[2*k+1] = a.y;
        }
    }
    __syncthreads();

    for (int p = tid; p < 650; p += 256) {
        int s = p % 50, uq = p / 50, u = uq*4;
        uint64_t a0 = 0, a1 = 0;
        #pragma unroll 4
        for (int e = 0; e < RPR; e++) {
            float q = qT[e*NA_QP + s];
            uint64_t pq = pk2(q, q);
            ulonglong2 xv = *(const ulonglong2*)(xT + e*NA_XP + u);
            fma2(a0, pq, xv.x); fma2(a1, pq, xv.y);
        }
        float2 r0 = up2(a0), r1 = up2(a1);
        float* ar = attn + s*51;
        ar[u] = r0.x*SCALE;
        if (u+1 < 50) ar[u+1] = r0.y*SCALE;
        if (u+2 < 50) { ar[u+2] = r1.x*SCALE; ar[u+3] = r1.y*SCALE; }
    }
    __syncthreads();

    if (tid < 50) {
        float* row = attn + tid*51;
        float m = row[0];
        for (int u = 1; u < 50; u++) m = fmaxf(m, row[u]);
        float sum = 0.f;
        for (int u = 0; u < 50; u++) { float e = __expf(row[u]-m); row[u]=e; sum+=e; }
        float inv = 1.f/sum;
        for (int u = 0; u < 50; u++) row[u] *= inv;
    }
    __syncthreads();

    for (int p = tid; p < 800; p += 256) {
        int s = p >> 4, v = p & 15;
        const float* ar = attn + s*51;
        float a = 0.f;
        #pragma unroll 10
        for (int u = 0; u < 50; u++) a += ar[u]*Vh[u*16 + v];
        g_nval[(b*HISN + s)*RPR + h*VDIM + v] = a;
    }
}

#define NP_SMEM_FLOATS (HISN*RPR + HISN)

__global__ __launch_bounds__(256, 2)
void news_pool_kernel(const float* __restrict__ Wk, const float* __restrict__ bk,
                      const float* __restrict__ qv)
{
    float* val = sm;
    float* wl  = sm + HISN*RPR;
    const int tid = threadIdx.x;
    const int b   = blockIdx.x;

    for (int p = tid; p < HISN*RPR; p += 256) val[p] = g_nval[b*HISN*RPR + p];
    if (tid < HISN) wl[tid] = 0.f;
    __syncthreads();

    for (int p = tid; p < HISN*50; p += 256) {
        int s = p/50, kq = p%50, k = kq*4;
        float4 b4 = *(const float4*)(bk + k);
        uint64_t a0 = pk2(b4.x, b4.y), a1 = pk2(b4.z, b4.w);
        const float* vr  = val + s*RPR;
        const float* wkp = Wk + k;
        #pragma unroll 8
        for (int r = 0; r < RPR; r++) {
            uint64_t pv = pk2(vr[r], vr[r]);
            ulonglong2 wv = *(const ulonglong2*)(wkp + r*QDQ);
            fma2(a0, pv, wv.x); fma2(a1, pv, wv.y);
        }
        float2 r0 = up2(a0), r1 = up2(a1);
        float4 q4 = *(const float4*)(qv + k);
        float ts = tanhf(r0.x)*q4.x + tanhf(r0.y)*q4.y + tanhf(r1.x)*q4.z + tanhf(r1.y)*q4.w;
        atomicAdd(&wl[s], ts);
    }
    __syncthreads();
    if (tid == 0) {
        float m = -1e30f;
        for (int s = 0; s < HISN; s++) { wl[s] *= SCALE; m = fmaxf(m, wl[s]); }
        float sum = 0.f;
        for (int s = 0; s < HISN; s++) { float e = __expf(wl[s]-m); wl[s]=e; sum+=e; }
        float inv = 1.f/sum;
        for (int s = 0; s < HISN; s++) wl[s] *= inv;
    }
    __syncthreads();
    if (tid < RPR) {
        float a = 0.f;
        #pragma unroll 10
        for (int s = 0; s < HISN; s++) a += wl[s] * val[s*RPR + tid];
        g_user[b*RPR + tid] = a;
    }
}

__global__ void score_kernel(float* __restrict__ out)
{
    __shared__ float sc[CDDN];
    const int b = blockIdx.x;
    const int w = threadIdx.x >> 5, lane = threadIdx.x & 31;
    if (w < CDDN) {
        const float* c = g_cdd + (b*CDDN + w)*RPR;
        const float* u = g_user + b*RPR;
        float a = 0.f;
        #pragma unroll
        for (int k = lane; k < RPR; k += 32) a += c[k]*u[k];
        #pragma unroll
        for (int off = 16; off; off >>= 1) a += __shfl_down_sync(0xffffffffu, a, off);
        if (lane == 0) sc[w] = a;
    }
    __syncthreads();
    if (threadIdx.x == 0) {
        float m = sc[0];
        for (int c = 1; c < CDDN; c++) m = fmaxf(m, sc[c]);
        float sum = 0.f;
        for (int c = 0; c < CDDN; c++) sum += __expf(sc[c]-m);
        float lse = logf(sum) + m;
        for (int c = 0; c < CDDN; c++) out[b*CDDN + c] = sc[c] - lse;
    }
}

// ================= launch =================
extern "C" void kernel_launch(void* const* d_in, const int* in_sizes, int n_in,
                              void* d_out, int out_size)
{
    (void)in_sizes; (void)n_in; (void)out_size;
    const int*   cand    = (const int*)d_in[0];
    const int*   clicked = (const int*)d_in[1];
    const float* emb     = (const float*)d_in[2];
    const float* Wq_w    = (const float*)d_in[3];
    const float* Wv_w    = (const float*)d_in[4];
    const float* Wk_w    = (const float*)d_in[5];
    const float* bk_w    = (const float*)d_in[6];
    const float* q_w     = (const float*)d_in[7];
    const float* Wq_n    = (const float*)d_in[8];
    const float* Wv_n    = (const float*)d_in[9];
    const float* Wk_n    = (const float*)d_in[10];
    const float* bk_n    = (const float*)d_in[11];
    const float* q_n     = (const float*)d_in[12];
    float* out = (float*)d_out;

    const size_t smw  = W_SMEM_FLOATS  * sizeof(float);
    const size_t smna = NA_SMEM_FLOATS * sizeof(float);
    const size_t smnp = NP_SMEM_FLOATS * sizeof(float);
    cudaFuncSetAttribute(word_kernel,      cudaFuncAttributeMaxDynamicSharedMemorySize, (int)smw);
    cudaFuncSetAttribute(news_attn_kernel, cudaFuncAttributeMaxDynamicSharedMemorySize, (int)smna);
    cudaFuncSetAttribute(news_pool_kernel, cudaFuncAttributeMaxDynamicSharedMemorySize, (int)smnp);

    conv_w_kernel<<<(KP*NPX + 255)/256, 256>>>(Wq_w, Wv_w);
    conv_x_kernel<<<NITEMS, 256>>>(cand, clicked, emb);

    for (int ch = 0; ch < NCHUNK; ch++) {
        qgemm_kernel<<<dim3(NPX/128, ROWS_PC/128), 512>>>(ch*ROWS_PC);
        word_kernel<<<ITEMS_PC, 640, smw>>>(ch*ITEMS_PC, cand, clicked, emb,
                                            Wk_w, bk_w, q_w);
    }

    news_attn_kernel<<<dim3(HH, BB), 256, smna>>>(Wq_n, Wv_n);
    news_pool_kernel<<<BB, 256, smnp>>>(Wk_n, bk_n, q_n);
    score_kernel<<<BB, 192>>>(out);
}